// round 13
// baseline (speedup 1.0000x reference)
#include <cuda_runtime.h>
#include <cuda_bf16.h>
#include <cuda_fp16.h>
#include <cstdint>

// Problem constants
#define BB 32
#define LL 4096
#define DD 512
#define MODES 64
#define NK 128          // 2*MODES (real rows + imag rows)
#define WSCALE 16384.0f // 2^14 fp16 range scaling for weights
#define AMSCALE 33554432.0f   // 2^25 fp16 range scaling for spectra
#define INV_AMSCALE (1.0f / 33554432.0f)

// ---------------------------------------------------------------------------
// Static device scratch
// ---------------------------------------------------------------------------
__device__ float   g_F1[NK * 2048];              // folded fwd tables [128][2048] (tf32)
__device__ __half  g_S3FH[1024 * 128];           // folded inv tables fp16
__device__ __half2 g_W2[2ull * MODES * 256 * DD];// [ri][m][d2][e] d-pair-interleaved, x2^14
__device__ __half  g_QH[BB * NK * DD];           // [b][row][d] fp16 spectra of q
__device__ __half  g_AmH[BB * 64 * DD * 2];      // [b][p2][e][slot] fp16, permuted+pair-interleaved, x2^25

// ---------------------------------------------------------------------------
// Helpers
// ---------------------------------------------------------------------------
__device__ __forceinline__ uint32_t f2tf(float f) {
    uint32_t u;
    asm("cvt.rna.tf32.f32 %0, %1;" : "=r"(u) : "f"(f));
    return u;
}
__device__ __forceinline__ float f2tf_f(float f) { return __uint_as_float(f2tf(f)); }

__device__ __forceinline__ void mma_tf32(float c[4],
                                         uint32_t a0, uint32_t a1, uint32_t a2, uint32_t a3,
                                         uint32_t b0, uint32_t b1) {
    asm volatile(
        "mma.sync.aligned.m16n8k8.row.col.f32.tf32.tf32.f32 "
        "{%0,%1,%2,%3}, {%4,%5,%6,%7}, {%8,%9}, {%0,%1,%2,%3};"
        : "+f"(c[0]), "+f"(c[1]), "+f"(c[2]), "+f"(c[3])
        : "r"(a0), "r"(a1), "r"(a2), "r"(a3), "r"(b0), "r"(b1));
}

__device__ __forceinline__ void mma_f16(float c[4],
                                        uint32_t a0, uint32_t a1, uint32_t a2, uint32_t a3,
                                        uint32_t b0, uint32_t b1) {
    asm volatile(
        "mma.sync.aligned.m16n8k16.row.col.f32.f16.f16.f32 "
        "{%0,%1,%2,%3}, {%4,%5,%6,%7}, {%8,%9}, {%0,%1,%2,%3};"
        : "+f"(c[0]), "+f"(c[1]), "+f"(c[2]), "+f"(c[3])
        : "r"(a0), "r"(a1), "r"(a2), "r"(a3), "r"(b0), "r"(b1));
}

__device__ __forceinline__ void cp16(uint32_t dst_smem, const void* src) {
    asm volatile("cp.async.cg.shared.global [%0], [%1], 16;" :: "r"(dst_smem), "l"(src));
}
__device__ __forceinline__ void cp_commit() { asm volatile("cp.async.commit_group;"); }

// ---------------------------------------------------------------------------
// Init: all twiddle tables in one launch.
// ---------------------------------------------------------------------------
#define F1_CNT (NK * 2048)
#define S3F_CNT (1024 * 128)

__global__ void fno_init() {
    int idx = blockIdx.x * blockDim.x + threadIdx.x;
    if (idx < F1_CNT) {
        int row = idx >> 11;
        int j   = idx & 2047;
        int l   = j + 1;
        int m   = row & (MODES - 1);
        int r   = (m * l) & (LL - 1);
        float s, c;
        sincospif((float)r * (1.0f / 2048.0f), &s, &c);
        g_F1[row * 2048 + j] = f2tf_f((row < MODES) ? c : -s);
    } else if (idx < F1_CNT + S3F_CNT) {
        int i2 = idx - F1_CNT;
        int l  = i2 >> 7;
        int cc = i2 & 127;
        int grp = cc >> 5;            // 0 cosE, 1 cosO, 2 -sinE, 3 -sinO
        int m  = ((cc & 31) << 1) + (grp & 1);
        int r  = (m * l) & (LL - 1);
        float s, c;
        sincospif((float)r * (1.0f / 2048.0f), &s, &c);
        g_S3FH[l * 128 + cc] = __float2half_rn((grp < 2) ? c : -s);
    }
}

// ---------------------------------------------------------------------------
// Weight transpose: g_W2[ri][m][d2][e] = half2(w_ri[2*d2][e][m], w_ri[2*d2+1][e][m]) * 2^14
// grid (16 e-tiles, 2 m-tiles, 256 d-pairs), block (32,8).
// ---------------------------------------------------------------------------
__global__ void fno_transpose_w(const float* __restrict__ wr,
                                const float* __restrict__ wi) {
    __shared__ float t[2][2][32][33];   // [ri][dd][e-idx][m-idx]
    int z  = blockIdx.z;                // d-pair index
    int e0 = blockIdx.x * 32;
    int m0 = blockIdx.y * 32;
    int tx = threadIdx.x, ty = threadIdx.y;
#pragma unroll
    for (int dd = 0; dd < 2; dd++) {
        int d = 2 * z + dd;
        size_t src = ((size_t)d * DD) * MODES + m0;
        for (int i = ty; i < 32; i += 8) {
            t[0][dd][i][tx] = wr[src + (size_t)(e0 + i) * MODES + tx];
            t[1][dd][i][tx] = wi[src + (size_t)(e0 + i) * MODES + tx];
        }
    }
    __syncthreads();
    for (int i = ty; i < 32; i += 8) {
        int m = m0 + i;
        size_t dstR = (((size_t)m) * 256 + z) * DD + e0 + tx;
        size_t dstI = dstR + (size_t)MODES * 256 * DD;
        g_W2[dstR] = __floats2half2_rn(t[0][0][tx][i] * WSCALE, t[0][1][tx][i] * WSCALE);
        g_W2[dstI] = __floats2half2_rn(t[1][0][tx][i] * WSCALE, t[1][1][tx][i] * WSCALE);
    }
}

// ===========================================================================
// Stage 1 (folded, tf32 MMA, BN=64) — epilogue -> g_QH fp16.
// ===========================================================================
#define F1_A_F (128 * 36)
#define F1_B_F (32 * 72)
#define S1F_SMEM ((2 * F1_A_F + 4 * F1_B_F) * 4)   // 73728

__global__ __launch_bounds__(256, 2) void fno_stage1_fold(const float* __restrict__ q) {
    extern __shared__ float sm[];
    float* Bbase = sm + 2 * F1_A_F;
    const int b  = blockIdx.y;
    const int n0 = blockIdx.x * 64;
    const float* qb = q + (size_t)b * LL * DD;
    const int tid = threadIdx.x;
    const int warp = tid >> 5, lane = tid & 31;
    const int wm = warp >> 2, wn = warp & 3;
    const int gid = lane >> 2, tig = lane & 3;
    const uint32_t smu = (uint32_t)__cvta_generic_to_shared(sm);

    float acc[4][2][4];
#pragma unroll
    for (int i = 0; i < 4; i++)
#pragma unroll
        for (int j = 0; j < 2; j++)
#pragma unroll
            for (int k = 0; k < 4; k++) acc[i][j][k] = 0.0f;

    float4 v1[2], v2[2];
    auto ldB = [&](int k0) {
#pragma unroll
        for (int i = 0; i < 2; i++) {
            int idx = tid + i * 256;
            int j = idx >> 4, c4 = idx & 15;
            int l = k0 + j + 1;
            v1[i] = *(const float4*)&qb[(size_t)l * DD + n0 + c4 * 4];
            if (l == 2048) {
                v2[i] = make_float4(0.f, 0.f, 0.f, 0.f);
            } else {
                v2[i] = *(const float4*)&qb[(size_t)(LL - l) * DD + n0 + c4 * 4];
            }
        }
    };
    auto stB = [&](int buf) {
        float* P = Bbase + buf * 2 * F1_B_F;
        float* Dn = P + F1_B_F;
#pragma unroll
        for (int i = 0; i < 2; i++) {
            int idx = tid + i * 256;
            int j = idx >> 4, c4 = idx & 15;
            float4 p, d;
            p.x = f2tf_f(v1[i].x + v2[i].x);  d.x = f2tf_f(v1[i].x - v2[i].x);
            p.y = f2tf_f(v1[i].y + v2[i].y);  d.y = f2tf_f(v1[i].y - v2[i].y);
            p.z = f2tf_f(v1[i].z + v2[i].z);  d.z = f2tf_f(v1[i].z - v2[i].z);
            p.w = f2tf_f(v1[i].w + v2[i].w);  d.w = f2tf_f(v1[i].w - v2[i].w);
            *(float4*)&P[j * 72 + c4 * 4]  = p;
            *(float4*)&Dn[j * 72 + c4 * 4] = d;
        }
    };
    auto cpA = [&](int buf, int k0) {
        uint32_t aB = smu + buf * F1_A_F * 4;
#pragma unroll
        for (int i = 0; i < 4; i++) {
            int idx = tid + i * 256;
            int row = idx >> 3, c4 = idx & 7;
            cp16(aB + (row * 36 + c4 * 4) * 4, &g_F1[row * 2048 + k0 + c4 * 4]);
        }
        cp_commit();
    };

    cpA(0, 0);
    ldB(0);
    const int NT = 64;
    for (int kt = 0; kt < NT; kt++) {
        int buf = kt & 1;
        stB(buf);
        if (kt + 1 < NT) {
            cpA(buf ^ 1, (kt + 1) * 32);
            asm volatile("cp.async.wait_group 1;");
        } else {
            asm volatile("cp.async.wait_group 0;");
        }
        __syncthreads();
        if (kt + 1 < NT) ldB((kt + 1) * 32);

        const float* As = sm + buf * F1_A_F;
        const float* Bs = Bbase + buf * 2 * F1_B_F + wm * F1_B_F;  // P or D
#pragma unroll
        for (int ks = 0; ks < 4; ks++) {
            uint32_t a[4][4];
#pragma unroll
            for (int tm = 0; tm < 4; tm++) {
                const float* ap = As + (wm * 64 + tm * 16 + gid) * 36 + ks * 8 + tig;
                a[tm][0] = __float_as_uint(ap[0]);
                a[tm][1] = __float_as_uint(ap[8 * 36]);
                a[tm][2] = __float_as_uint(ap[4]);
                a[tm][3] = __float_as_uint(ap[8 * 36 + 4]);
            }
            uint32_t bf[2][2];
#pragma unroll
            for (int tn = 0; tn < 2; tn++) {
                const float* bp = Bs + (ks * 8 + tig) * 72 + wn * 16 + tn * 8 + gid;
                bf[tn][0] = __float_as_uint(bp[0]);
                bf[tn][1] = __float_as_uint(bp[4 * 72]);
            }
#pragma unroll
            for (int tm = 0; tm < 4; tm++)
#pragma unroll
                for (int tn = 0; tn < 2; tn++)
                    mma_tf32(acc[tm][tn], a[tm][0], a[tm][1], a[tm][2], a[tm][3],
                             bf[tn][0], bf[tn][1]);
        }
        __syncthreads();
    }

#pragma unroll
    for (int tm = 0; tm < 4; tm++) {
        int r = wm * 64 + tm * 16 + gid;
#pragma unroll
        for (int tn = 0; tn < 2; tn++) {
            int c = n0 + wn * 16 + tn * 8 + tig * 2;
            float c0 = 0.f, c1 = 0.f;
            if (wm == 0) { c0 = qb[c]; c1 = qb[c + 1]; }
            *(__half2*)&g_QH[((size_t)b * NK + r) * DD + c] =
                __floats2half2_rn(acc[tm][tn][0] + c0, acc[tm][tn][1] + c1);
            *(__half2*)&g_QH[((size_t)b * NK + r + 8) * DD + c] =
                __floats2half2_rn(acc[tm][tn][2] + c0, acc[tm][tn][3] + c1);
        }
    }
}

// ---------------------------------------------------------------------------
// Stage 2 (fp16 MMA m16n8k16): per-mode complex GEMM, chunked by e-tile.
// A: g_QH [64 rows (ri,b)][32 d halves], pitch 80B.
// B: g_W2 [32 rows (ri,d2)][128 e half2], pitch 560B.
// Epilogue writes g_AmH (fp16, stage3-permuted, x2^25).
// ---------------------------------------------------------------------------
#define S2_A_PITCH 80                      // bytes/row
#define S2_B_PITCH 560                     // bytes/row
#define S2_A_BYTES (64 * S2_A_PITCH)       // 5120
#define S2_B_BYTES (32 * S2_B_PITCH)       // 17920
#define S2_BUF_BYTES (S2_A_BYTES + S2_B_BYTES)
#define S2_SMEM (2 * S2_BUF_BYTES)         // 46080

__global__ __launch_bounds__(256) void fno_stage2_mma(int e0) {
    extern __shared__ char smc[];
    const int m  = blockIdx.y;
    const int tid = threadIdx.x;
    const int warp = tid >> 5, lane = tid & 31;
    const int wm = warp >> 2;
    const int wn = warp & 3;
    const int gid = lane >> 2, tig = lane & 3;
    const uint32_t smem_u = (uint32_t)__cvta_generic_to_shared(smc);

    float accR[4][4], accI[4][4];
#pragma unroll
    for (int i = 0; i < 4; i++)
#pragma unroll
        for (int j = 0; j < 4; j++) { accR[i][j] = 0.0f; accI[i][j] = 0.0f; }

    auto load_tiles = [&](int buf, int kt) {
        uint32_t aB = smem_u + buf * S2_BUF_BYTES;
        uint32_t bB = aB + S2_A_BYTES;
        int d0 = kt * 32;
        // A: 64 rows x 64B -> 256 cp16 (1/thread)
        {
            int row = tid >> 2, c16 = tid & 3;
            int ri = row >> 5, bb = row & 31;
            cp16(aB + row * S2_A_PITCH + c16 * 16,
                 &g_QH[((size_t)bb * NK + ri * MODES + m) * DD + d0 + c16 * 8]);
        }
        // B: 32 rows x 512B -> 1024 cp16 (4/thread)
#pragma unroll
        for (int i = 0; i < 4; i++) {
            int idx = tid + i * 256;
            int row = idx >> 5, c = idx & 31;
            int ri = row >> 4, dr = row & 15;
            int d2 = kt * 16 + dr;
            cp16(bB + row * S2_B_PITCH + c * 16,
                 &g_W2[(((size_t)ri * MODES + m) * 256 + d2) * DD + e0 + c * 4]);
        }
        cp_commit();
    };

    load_tiles(0, 0);
    int buf = 0;
    const int NT = 16;
    for (int kt = 0; kt < NT; kt++) {
        if (kt + 1 < NT) {
            load_tiles(buf ^ 1, kt + 1);
            asm volatile("cp.async.wait_group 1;");
        } else {
            asm volatile("cp.async.wait_group 0;");
        }
        __syncthreads();
        const char* As = smc + buf * S2_BUF_BYTES;
        const char* Bs = As + S2_A_BYTES;
#pragma unroll
        for (int ks = 0; ks < 2; ks++) {
            uint32_t ar[4], ai[4];
            {
                const char* ap = As + (wm * 16 + gid) * S2_A_PITCH + ks * 32 + tig * 4;
                ar[0] = *(const uint32_t*)(ap);
                ar[1] = *(const uint32_t*)(ap + 8 * S2_A_PITCH);
                ar[2] = *(const uint32_t*)(ap + 16);
                ar[3] = *(const uint32_t*)(ap + 8 * S2_A_PITCH + 16);
                const char* aq = ap + 32 * S2_A_PITCH;
                ai[0] = *(const uint32_t*)(aq);
                ai[1] = *(const uint32_t*)(aq + 8 * S2_A_PITCH);
                ai[2] = *(const uint32_t*)(aq + 16);
                ai[3] = *(const uint32_t*)(aq + 8 * S2_A_PITCH + 16);
            }
#pragma unroll
            for (int tn = 0; tn < 4; tn++) {
                const char* bpR = Bs + (ks * 8 + tig) * S2_B_PITCH + (wn * 32 + tn * 8 + gid) * 4;
                uint32_t br0 = *(const uint32_t*)(bpR);
                uint32_t br1 = *(const uint32_t*)(bpR + 4 * S2_B_PITCH);
                const char* bpI = bpR + 16 * S2_B_PITCH;
                uint32_t bi0 = *(const uint32_t*)(bpI);
                uint32_t bi1 = *(const uint32_t*)(bpI + 4 * S2_B_PITCH);
                mma_f16(accR[tn], ar[0], ar[1], ar[2], ar[3], br0, br1);
                mma_f16(accR[tn], ai[0], ai[1], ai[2], ai[3],
                        bi0 ^ 0x80008000u, bi1 ^ 0x80008000u);
                mma_f16(accI[tn], ar[0], ar[1], ar[2], ar[3], bi0, bi1);
                mma_f16(accI[tn], ai[0], ai[1], ai[2], ai[3], br0, br1);
            }
        }
        __syncthreads();
        buf ^= 1;
    }

    // epilogue: write fp16 spectra in stage3 layout.
    const float cfac = ((m == 0) ? 1.0f : 2.0f) * (AMSCALE / ((float)LL * WSCALE));
    const int mh  = m >> 1;
    const int pr  = (m & 1) ? (32 + mh) : mh;
    const int pi  = pr + 64;
    const int p2r = pr >> 1, slr = pr & 1;
    const int p2i = pi >> 1, sli = pi & 1;
#pragma unroll
    for (int tn = 0; tn < 4; tn++) {
        int c = e0 + wn * 32 + tn * 8 + tig * 2;
        int b0r = wm * 16 + gid;
#pragma unroll
        for (int h = 0; h < 2; h++) {
            int bb = b0r + h * 8;
            size_t baseR = (((size_t)bb * 64 + p2r) * DD) * 2 + slr;
            size_t baseI = (((size_t)bb * 64 + p2i) * DD) * 2 + sli;
            g_AmH[baseR + (size_t)(c)     * 2] = __float2half_rn(cfac * accR[tn][h * 2]);
            g_AmH[baseR + (size_t)(c + 1) * 2] = __float2half_rn(cfac * accR[tn][h * 2 + 1]);
            g_AmH[baseI + (size_t)(c)     * 2] = __float2half_rn(cfac * accI[tn][h * 2]);
            g_AmH[baseI + (size_t)(c + 1) * 2] = __float2half_rn(cfac * accI[tn][h * 2 + 1]);
        }
    }
}

// ===========================================================================
// Stage 3 (double-folded, fp16 MMA m16n8k16) — chunked by e via xoff.
// ===========================================================================
#define T3H_A_BYTES (64 * 272)
#define T3H_B_BYTES (64 * 272)
#define T3H_SMEM (T3H_A_BYTES + T3H_B_BYTES)   // 34816

__global__ __launch_bounds__(256, 2) void fno_stage3_fold2(float* __restrict__ out, int xoff) {
    extern __shared__ char smc[];
    const int b  = blockIdx.z;
    const int l0 = blockIdx.y * 64;
    const int n0 = (xoff + blockIdx.x) * 64;
    const int tid = threadIdx.x;
    const int warp = tid >> 5, lane = tid & 31;
    const int wm = warp >> 2, wn = warp & 3;
    const int gid = lane >> 2, tig = lane & 3;
    const uint32_t smem_u = (uint32_t)__cvta_generic_to_shared(smc);
    const char* As = smc;
    const char* Bs = smc + T3H_A_BYTES;
    const __half2* gah = (const __half2*)g_AmH;

    {
        uint32_t aB = smem_u;
        uint32_t bB = smem_u + T3H_A_BYTES;
#pragma unroll
        for (int i = 0; i < 4; i++) {
            int idx = tid + i * 256;
            int row = idx >> 4, c16 = idx & 15;
            cp16(aB + row * 272 + c16 * 16, &g_S3FH[(l0 + row) * 128 + c16 * 8]);
        }
#pragma unroll
        for (int i = 0; i < 4; i++) {
            int idx = tid + i * 256;
            int row = idx >> 4, c4 = idx & 15;
            cp16(bB + row * 272 + c4 * 16,
                 &gah[((size_t)(b * 64 + row)) * DD + n0 + c4 * 4]);
        }
        cp_commit();
        asm volatile("cp.async.wait_group 0;");
        __syncthreads();
    }

    float aCE[2][2][4], aCO[2][2][4], aSE[2][2][4], aSO[2][2][4];
#pragma unroll
    for (int i = 0; i < 2; i++)
#pragma unroll
        for (int j = 0; j < 2; j++)
#pragma unroll
            for (int k = 0; k < 4; k++) {
                aCE[i][j][k] = 0.0f; aCO[i][j][k] = 0.0f;
                aSE[i][j][k] = 0.0f; aSO[i][j][k] = 0.0f;
            }

#pragma unroll
    for (int ks = 0; ks < 8; ks++) {
        uint32_t a[2][4];
#pragma unroll
        for (int tm = 0; tm < 2; tm++) {
            const char* ap = As + (wm * 32 + tm * 16 + gid) * 272 + (ks * 16 + 2 * tig) * 2;
            a[tm][0] = *(const uint32_t*)(ap);
            a[tm][1] = *(const uint32_t*)(ap + 8 * 272);
            a[tm][2] = *(const uint32_t*)(ap + 16);
            a[tm][3] = *(const uint32_t*)(ap + 8 * 272 + 16);
        }
        uint32_t bf[2][2];
#pragma unroll
        for (int tn = 0; tn < 2; tn++) {
            const char* bp = Bs + (ks * 8 + tig) * 272 + (wn * 16 + tn * 8 + gid) * 4;
            bf[tn][0] = *(const uint32_t*)(bp);
            bf[tn][1] = *(const uint32_t*)(bp + 4 * 272);
        }
        if (ks < 2) {
#pragma unroll
            for (int tm = 0; tm < 2; tm++)
#pragma unroll
                for (int tn = 0; tn < 2; tn++)
                    mma_f16(aCE[tm][tn], a[tm][0], a[tm][1], a[tm][2], a[tm][3],
                            bf[tn][0], bf[tn][1]);
        } else if (ks < 4) {
#pragma unroll
            for (int tm = 0; tm < 2; tm++)
#pragma unroll
                for (int tn = 0; tn < 2; tn++)
                    mma_f16(aCO[tm][tn], a[tm][0], a[tm][1], a[tm][2], a[tm][3],
                            bf[tn][0], bf[tn][1]);
        } else if (ks < 6) {
#pragma unroll
            for (int tm = 0; tm < 2; tm++)
#pragma unroll
                for (int tn = 0; tn < 2; tn++)
                    mma_f16(aSE[tm][tn], a[tm][0], a[tm][1], a[tm][2], a[tm][3],
                            bf[tn][0], bf[tn][1]);
        } else {
#pragma unroll
            for (int tm = 0; tm < 2; tm++)
#pragma unroll
                for (int tn = 0; tn < 2; tn++)
                    mma_f16(aSO[tm][tn], a[tm][0], a[tm][1], a[tm][2], a[tm][3],
                            bf[tn][0], bf[tn][1]);
        }
    }

    float* ob = out + (size_t)b * LL * DD;
#pragma unroll
    for (int tm = 0; tm < 2; tm++) {
        int lA = l0 + wm * 32 + tm * 16 + gid;
#pragma unroll
        for (int tn = 0; tn < 2; tn++) {
            int c = n0 + wn * 16 + tn * 8 + tig * 2;
#pragma unroll
            for (int h = 0; h < 2; h++) {
                int l = lA + h * 8;
                float ce0 = aCE[tm][tn][h * 2],     ce1 = aCE[tm][tn][h * 2 + 1];
                float co0 = aCO[tm][tn][h * 2],     co1 = aCO[tm][tn][h * 2 + 1];
                float se0 = aSE[tm][tn][h * 2],     se1 = aSE[tm][tn][h * 2 + 1];
                float so0 = aSO[tm][tn][h * 2],     so1 = aSO[tm][tn][h * 2 + 1];
                *(float2*)&ob[(size_t)l * DD + c] =
                    make_float2((ce0 + co0 + se0 + so0) * INV_AMSCALE,
                                (ce1 + co1 + se1 + so1) * INV_AMSCALE);
                *(float2*)&ob[(size_t)(2048 - l) * DD + c] =
                    make_float2((ce0 - co0 - se0 + so0) * INV_AMSCALE,
                                (ce1 - co1 - se1 + so1) * INV_AMSCALE);
                *(float2*)&ob[(size_t)(2048 + l) * DD + c] =
                    make_float2((ce0 - co0 + se0 - so0) * INV_AMSCALE,
                                (ce1 - co1 + se1 - so1) * INV_AMSCALE);
                if (l > 0)
                    *(float2*)&ob[(size_t)(LL - l) * DD + c] =
                        make_float2((ce0 + co0 - se0 - so0) * INV_AMSCALE,
                                    (ce1 + co1 - se1 - so1) * INV_AMSCALE);
            }
        }
    }
}

// ---------------------------------------------------------------------------
// Rows l=1024 and l=3072
// ---------------------------------------------------------------------------
__global__ void fno_rows_special(float* __restrict__ out) {
    int b = blockIdx.y;
    int e = blockIdx.x * 128 + threadIdx.x;
    float C = 0.0f, S = 0.0f;
#pragma unroll
    for (int j = 0; j < 32; j++) {
        float sgn = (j & 1) ? -1.0f : 1.0f;
        float ar = __half2float(g_AmH[(((size_t)b * 64 + (j >> 1)) * DD + e) * 2 + (j & 1)]);
        float ai = __half2float(g_AmH[(((size_t)b * 64 + 48 + (j >> 1)) * DD + e) * 2 + (j & 1)]);
        C += sgn * ar;
        S -= sgn * ai;
    }
    out[((size_t)b * LL + 1024) * DD + e] = (C + S) * INV_AMSCALE;
    out[((size_t)b * LL + 3072) * DD + e] = (C - S) * INV_AMSCALE;
}

// ---------------------------------------------------------------------------
// Launch: transpose on side stream overlapping stage1; stage2/stage3 chunked
// by e-tile and pipelined across the two streams via per-chunk events.
// ---------------------------------------------------------------------------
extern "C" void kernel_launch(void* const* d_in, const int* in_sizes, int n_in,
                              void* d_out, int out_size) {
    (void)in_sizes; (void)n_in; (void)out_size;
    const float* q  = (const float*)d_in[0];
    const float* wr = (const float*)d_in[1];
    const float* wi = (const float*)d_in[2];
    float* out = (float*)d_out;

    static bool init_done = false;
    static cudaStream_t s_side;
    static cudaEvent_t ev_fork, ev_join, ev_end;
    static cudaEvent_t ev2[4];
    if (!init_done) {
        cudaFuncSetAttribute(fno_stage1_fold,
                             cudaFuncAttributeMaxDynamicSharedMemorySize, S1F_SMEM);
        cudaFuncSetAttribute(fno_stage2_mma,
                             cudaFuncAttributeMaxDynamicSharedMemorySize, S2_SMEM);
        cudaFuncSetAttribute(fno_stage3_fold2,
                             cudaFuncAttributeMaxDynamicSharedMemorySize, T3H_SMEM);
        cudaStreamCreateWithFlags(&s_side, cudaStreamNonBlocking);
        cudaEventCreateWithFlags(&ev_fork, cudaEventDisableTiming);
        cudaEventCreateWithFlags(&ev_join, cudaEventDisableTiming);
        cudaEventCreateWithFlags(&ev_end, cudaEventDisableTiming);
        for (int c = 0; c < 4; c++)
            cudaEventCreateWithFlags(&ev2[c], cudaEventDisableTiming);
        init_done = true;
    }

    // main: tables
    fno_init<<<(F1_CNT + S3F_CNT + 255) / 256, 256>>>();

    // fork: transpose on side stream, concurrent with stage1
    cudaEventRecord(ev_fork, 0);
    cudaStreamWaitEvent(s_side, ev_fork, 0);
    fno_transpose_w<<<dim3(16, 2, 256), dim3(32, 8), 0, s_side>>>(wr, wi);

    fno_stage1_fold<<<dim3(8, 32), 256, S1F_SMEM>>>(q);

    // join: stage2 needs g_QH (main) and g_W2 (side)
    cudaEventRecord(ev_join, s_side);
    cudaStreamWaitEvent(0, ev_join, 0);

    // pipelined stage2 (main) -> stage3 (side), chunked by e-tile of 128
    for (int c = 0; c < 4; c++) {
        fno_stage2_mma<<<dim3(1, 64), 256, S2_SMEM>>>(c * 128);
        cudaEventRecord(ev2[c], 0);
        cudaStreamWaitEvent(s_side, ev2[c], 0);
        fno_stage3_fold2<<<dim3(2, 16, 32), 256, T3H_SMEM, s_side>>>(out, 2 * c);
    }

    // rows_special needs all of g_AmH; runs on main concurrent with side stage3
    fno_rows_special<<<dim3(4, 32), 128>>>(out);

    // final join
    cudaEventRecord(ev_end, s_side);
    cudaStreamWaitEvent(0, ev_end, 0);
}

// round 14
// speedup vs baseline: 1.3711x; 1.3711x over previous
#include <cuda_runtime.h>
#include <cuda_bf16.h>
#include <cuda_fp16.h>
#include <cstdint>

// Problem constants
#define BB 32
#define LL 4096
#define DD 512
#define MODES 64
#define NK 128          // 2*MODES (real rows + imag rows)
#define WSCALE 16384.0f // 2^14 fp16 range scaling for weights
#define AMSCALE 33554432.0f   // 2^25 fp16 range scaling for spectra
#define INV_AMSCALE (1.0f / 33554432.0f)

// ---------------------------------------------------------------------------
// Static device scratch
// ---------------------------------------------------------------------------
__device__ float   g_F1[NK * 2048];              // folded fwd tables [128][2048] (tf32)
__device__ __half  g_S3FH[1024 * 128];           // folded inv tables fp16
__device__ __half2 g_W2[2ull * MODES * 256 * DD];// [ri][m][d2][e] d-pair-interleaved, x2^14
__device__ __half  g_QH[BB * NK * DD];           // [b][row][d] fp16 spectra of q
__device__ __half  g_AmH[BB * 64 * DD * 2];      // [b][p2][e][slot] fp16, permuted+pair-interleaved, x2^25

// ---------------------------------------------------------------------------
// Helpers
// ---------------------------------------------------------------------------
__device__ __forceinline__ uint32_t f2tf(float f) {
    uint32_t u;
    asm("cvt.rna.tf32.f32 %0, %1;" : "=r"(u) : "f"(f));
    return u;
}
__device__ __forceinline__ float f2tf_f(float f) { return __uint_as_float(f2tf(f)); }

__device__ __forceinline__ void mma_tf32(float c[4],
                                         uint32_t a0, uint32_t a1, uint32_t a2, uint32_t a3,
                                         uint32_t b0, uint32_t b1) {
    asm volatile(
        "mma.sync.aligned.m16n8k8.row.col.f32.tf32.tf32.f32 "
        "{%0,%1,%2,%3}, {%4,%5,%6,%7}, {%8,%9}, {%0,%1,%2,%3};"
        : "+f"(c[0]), "+f"(c[1]), "+f"(c[2]), "+f"(c[3])
        : "r"(a0), "r"(a1), "r"(a2), "r"(a3), "r"(b0), "r"(b1));
}

__device__ __forceinline__ void mma_f16(float c[4],
                                        uint32_t a0, uint32_t a1, uint32_t a2, uint32_t a3,
                                        uint32_t b0, uint32_t b1) {
    asm volatile(
        "mma.sync.aligned.m16n8k16.row.col.f32.f16.f16.f32 "
        "{%0,%1,%2,%3}, {%4,%5,%6,%7}, {%8,%9}, {%0,%1,%2,%3};"
        : "+f"(c[0]), "+f"(c[1]), "+f"(c[2]), "+f"(c[3])
        : "r"(a0), "r"(a1), "r"(a2), "r"(a3), "r"(b0), "r"(b1));
}

__device__ __forceinline__ void cp16(uint32_t dst_smem, const void* src) {
    asm volatile("cp.async.cg.shared.global [%0], [%1], 16;" :: "r"(dst_smem), "l"(src));
}
__device__ __forceinline__ void cp_commit() { asm volatile("cp.async.commit_group;"); }

// ---------------------------------------------------------------------------
// Init: all twiddle tables in one launch.
// ---------------------------------------------------------------------------
#define F1_CNT (NK * 2048)
#define S3F_CNT (1024 * 128)

__global__ void fno_init() {
    int idx = blockIdx.x * blockDim.x + threadIdx.x;
    if (idx < F1_CNT) {
        int row = idx >> 11;
        int j   = idx & 2047;
        int l   = j + 1;
        int m   = row & (MODES - 1);
        int r   = (m * l) & (LL - 1);
        float s, c;
        sincospif((float)r * (1.0f / 2048.0f), &s, &c);
        g_F1[row * 2048 + j] = f2tf_f((row < MODES) ? c : -s);
    } else if (idx < F1_CNT + S3F_CNT) {
        int i2 = idx - F1_CNT;
        int l  = i2 >> 7;
        int cc = i2 & 127;
        int grp = cc >> 5;            // 0 cosE, 1 cosO, 2 -sinE, 3 -sinO
        int m  = ((cc & 31) << 1) + (grp & 1);
        int r  = (m * l) & (LL - 1);
        float s, c;
        sincospif((float)r * (1.0f / 2048.0f), &s, &c);
        g_S3FH[l * 128 + cc] = __float2half_rn((grp < 2) ? c : -s);
    }
}

// ---------------------------------------------------------------------------
// Weight transpose: g_W2[ri][m][d2][e] = half2(w_ri[2*d2][e][m], w_ri[2*d2+1][e][m]) * 2^14
// grid (16 e-tiles, 2 m-tiles, 256 d-pairs), block (32,8).
// ---------------------------------------------------------------------------
__global__ void fno_transpose_w(const float* __restrict__ wr,
                                const float* __restrict__ wi) {
    __shared__ float t[2][2][32][33];   // [ri][dd][e-idx][m-idx]
    int z  = blockIdx.z;                // d-pair index
    int e0 = blockIdx.x * 32;
    int m0 = blockIdx.y * 32;
    int tx = threadIdx.x, ty = threadIdx.y;
#pragma unroll
    for (int dd = 0; dd < 2; dd++) {
        int d = 2 * z + dd;
        size_t src = ((size_t)d * DD) * MODES + m0;
        for (int i = ty; i < 32; i += 8) {
            t[0][dd][i][tx] = wr[src + (size_t)(e0 + i) * MODES + tx];
            t[1][dd][i][tx] = wi[src + (size_t)(e0 + i) * MODES + tx];
        }
    }
    __syncthreads();
    for (int i = ty; i < 32; i += 8) {
        int m = m0 + i;
        size_t dstR = (((size_t)m) * 256 + z) * DD + e0 + tx;
        size_t dstI = dstR + (size_t)MODES * 256 * DD;
        g_W2[dstR] = __floats2half2_rn(t[0][0][tx][i] * WSCALE, t[0][1][tx][i] * WSCALE);
        g_W2[dstI] = __floats2half2_rn(t[1][0][tx][i] * WSCALE, t[1][1][tx][i] * WSCALE);
    }
}

// ===========================================================================
// Stage 1 (folded, tf32 MMA, BN=64) — epilogue -> g_QH fp16.
// ===========================================================================
#define F1_A_F (128 * 36)
#define F1_B_F (32 * 72)
#define S1F_SMEM ((2 * F1_A_F + 4 * F1_B_F) * 4)   // 73728

__global__ __launch_bounds__(256, 2) void fno_stage1_fold(const float* __restrict__ q) {
    extern __shared__ float sm[];
    float* Bbase = sm + 2 * F1_A_F;
    const int b  = blockIdx.y;
    const int n0 = blockIdx.x * 64;
    const float* qb = q + (size_t)b * LL * DD;
    const int tid = threadIdx.x;
    const int warp = tid >> 5, lane = tid & 31;
    const int wm = warp >> 2, wn = warp & 3;
    const int gid = lane >> 2, tig = lane & 3;
    const uint32_t smu = (uint32_t)__cvta_generic_to_shared(sm);

    float acc[4][2][4];
#pragma unroll
    for (int i = 0; i < 4; i++)
#pragma unroll
        for (int j = 0; j < 2; j++)
#pragma unroll
            for (int k = 0; k < 4; k++) acc[i][j][k] = 0.0f;

    float4 v1[2], v2[2];
    auto ldB = [&](int k0) {
#pragma unroll
        for (int i = 0; i < 2; i++) {
            int idx = tid + i * 256;
            int j = idx >> 4, c4 = idx & 15;
            int l = k0 + j + 1;
            v1[i] = *(const float4*)&qb[(size_t)l * DD + n0 + c4 * 4];
            if (l == 2048) {
                v2[i] = make_float4(0.f, 0.f, 0.f, 0.f);
            } else {
                v2[i] = *(const float4*)&qb[(size_t)(LL - l) * DD + n0 + c4 * 4];
            }
        }
    };
    auto stB = [&](int buf) {
        float* P = Bbase + buf * 2 * F1_B_F;
        float* Dn = P + F1_B_F;
#pragma unroll
        for (int i = 0; i < 2; i++) {
            int idx = tid + i * 256;
            int j = idx >> 4, c4 = idx & 15;
            float4 p, d;
            p.x = f2tf_f(v1[i].x + v2[i].x);  d.x = f2tf_f(v1[i].x - v2[i].x);
            p.y = f2tf_f(v1[i].y + v2[i].y);  d.y = f2tf_f(v1[i].y - v2[i].y);
            p.z = f2tf_f(v1[i].z + v2[i].z);  d.z = f2tf_f(v1[i].z - v2[i].z);
            p.w = f2tf_f(v1[i].w + v2[i].w);  d.w = f2tf_f(v1[i].w - v2[i].w);
            *(float4*)&P[j * 72 + c4 * 4]  = p;
            *(float4*)&Dn[j * 72 + c4 * 4] = d;
        }
    };
    auto cpA = [&](int buf, int k0) {
        uint32_t aB = smu + buf * F1_A_F * 4;
#pragma unroll
        for (int i = 0; i < 4; i++) {
            int idx = tid + i * 256;
            int row = idx >> 3, c4 = idx & 7;
            cp16(aB + (row * 36 + c4 * 4) * 4, &g_F1[row * 2048 + k0 + c4 * 4]);
        }
        cp_commit();
    };

    cpA(0, 0);
    ldB(0);
    const int NT = 64;
    for (int kt = 0; kt < NT; kt++) {
        int buf = kt & 1;
        stB(buf);
        if (kt + 1 < NT) {
            cpA(buf ^ 1, (kt + 1) * 32);
            asm volatile("cp.async.wait_group 1;");
        } else {
            asm volatile("cp.async.wait_group 0;");
        }
        __syncthreads();
        if (kt + 1 < NT) ldB((kt + 1) * 32);

        const float* As = sm + buf * F1_A_F;
        const float* Bs = Bbase + buf * 2 * F1_B_F + wm * F1_B_F;  // P or D
#pragma unroll
        for (int ks = 0; ks < 4; ks++) {
            uint32_t a[4][4];
#pragma unroll
            for (int tm = 0; tm < 4; tm++) {
                const float* ap = As + (wm * 64 + tm * 16 + gid) * 36 + ks * 8 + tig;
                a[tm][0] = __float_as_uint(ap[0]);
                a[tm][1] = __float_as_uint(ap[8 * 36]);
                a[tm][2] = __float_as_uint(ap[4]);
                a[tm][3] = __float_as_uint(ap[8 * 36 + 4]);
            }
            uint32_t bf[2][2];
#pragma unroll
            for (int tn = 0; tn < 2; tn++) {
                const float* bp = Bs + (ks * 8 + tig) * 72 + wn * 16 + tn * 8 + gid;
                bf[tn][0] = __float_as_uint(bp[0]);
                bf[tn][1] = __float_as_uint(bp[4 * 72]);
            }
#pragma unroll
            for (int tm = 0; tm < 4; tm++)
#pragma unroll
                for (int tn = 0; tn < 2; tn++)
                    mma_tf32(acc[tm][tn], a[tm][0], a[tm][1], a[tm][2], a[tm][3],
                             bf[tn][0], bf[tn][1]);
        }
        __syncthreads();
    }

#pragma unroll
    for (int tm = 0; tm < 4; tm++) {
        int r = wm * 64 + tm * 16 + gid;
#pragma unroll
        for (int tn = 0; tn < 2; tn++) {
            int c = n0 + wn * 16 + tn * 8 + tig * 2;
            float c0 = 0.f, c1 = 0.f;
            if (wm == 0) { c0 = qb[c]; c1 = qb[c + 1]; }
            *(__half2*)&g_QH[((size_t)b * NK + r) * DD + c] =
                __floats2half2_rn(acc[tm][tn][0] + c0, acc[tm][tn][1] + c1);
            *(__half2*)&g_QH[((size_t)b * NK + r + 8) * DD + c] =
                __floats2half2_rn(acc[tm][tn][2] + c0, acc[tm][tn][3] + c1);
        }
    }
}

// ---------------------------------------------------------------------------
// Stage 2 (fp16 MMA m16n8k16): per-mode complex GEMM, monolithic grid (4,64).
// A: g_QH [64 rows (ri,b)][32 d halves], pitch 80B.
// B: g_W2 [32 rows (ri,d2)][128 e half2], pitch 560B.
// Epilogue writes g_AmH (fp16, stage3-permuted, x2^25).
// ---------------------------------------------------------------------------
#define S2_A_PITCH 80                      // bytes/row
#define S2_B_PITCH 560                     // bytes/row
#define S2_A_BYTES (64 * S2_A_PITCH)       // 5120
#define S2_B_BYTES (32 * S2_B_PITCH)       // 17920
#define S2_BUF_BYTES (S2_A_BYTES + S2_B_BYTES)
#define S2_SMEM (2 * S2_BUF_BYTES)         // 46080

__global__ __launch_bounds__(256) void fno_stage2_mma() {
    extern __shared__ char smc[];
    const int m  = blockIdx.y;
    const int e0 = blockIdx.x * 128;
    const int tid = threadIdx.x;
    const int warp = tid >> 5, lane = tid & 31;
    const int wm = warp >> 2;
    const int wn = warp & 3;
    const int gid = lane >> 2, tig = lane & 3;
    const uint32_t smem_u = (uint32_t)__cvta_generic_to_shared(smc);

    float accR[4][4], accI[4][4];
#pragma unroll
    for (int i = 0; i < 4; i++)
#pragma unroll
        for (int j = 0; j < 4; j++) { accR[i][j] = 0.0f; accI[i][j] = 0.0f; }

    auto load_tiles = [&](int buf, int kt) {
        uint32_t aB = smem_u + buf * S2_BUF_BYTES;
        uint32_t bB = aB + S2_A_BYTES;
        int d0 = kt * 32;
        // A: 64 rows x 64B -> 256 cp16 (1/thread)
        {
            int row = tid >> 2, c16 = tid & 3;
            int ri = row >> 5, bb = row & 31;
            cp16(aB + row * S2_A_PITCH + c16 * 16,
                 &g_QH[((size_t)bb * NK + ri * MODES + m) * DD + d0 + c16 * 8]);
        }
        // B: 32 rows x 512B -> 1024 cp16 (4/thread)
#pragma unroll
        for (int i = 0; i < 4; i++) {
            int idx = tid + i * 256;
            int row = idx >> 5, c = idx & 31;
            int ri = row >> 4, dr = row & 15;
            int d2 = kt * 16 + dr;
            cp16(bB + row * S2_B_PITCH + c * 16,
                 &g_W2[(((size_t)ri * MODES + m) * 256 + d2) * DD + e0 + c * 4]);
        }
        cp_commit();
    };

    load_tiles(0, 0);
    int buf = 0;
    const int NT = 16;
    for (int kt = 0; kt < NT; kt++) {
        if (kt + 1 < NT) {
            load_tiles(buf ^ 1, kt + 1);
            asm volatile("cp.async.wait_group 1;");
        } else {
            asm volatile("cp.async.wait_group 0;");
        }
        __syncthreads();
        const char* As = smc + buf * S2_BUF_BYTES;
        const char* Bs = As + S2_A_BYTES;
#pragma unroll
        for (int ks = 0; ks < 2; ks++) {
            uint32_t ar[4], ai[4];
            {
                const char* ap = As + (wm * 16 + gid) * S2_A_PITCH + ks * 32 + tig * 4;
                ar[0] = *(const uint32_t*)(ap);
                ar[1] = *(const uint32_t*)(ap + 8 * S2_A_PITCH);
                ar[2] = *(const uint32_t*)(ap + 16);
                ar[3] = *(const uint32_t*)(ap + 8 * S2_A_PITCH + 16);
                const char* aq = ap + 32 * S2_A_PITCH;
                ai[0] = *(const uint32_t*)(aq);
                ai[1] = *(const uint32_t*)(aq + 8 * S2_A_PITCH);
                ai[2] = *(const uint32_t*)(aq + 16);
                ai[3] = *(const uint32_t*)(aq + 8 * S2_A_PITCH + 16);
            }
#pragma unroll
            for (int tn = 0; tn < 4; tn++) {
                const char* bpR = Bs + (ks * 8 + tig) * S2_B_PITCH + (wn * 32 + tn * 8 + gid) * 4;
                uint32_t br0 = *(const uint32_t*)(bpR);
                uint32_t br1 = *(const uint32_t*)(bpR + 4 * S2_B_PITCH);
                const char* bpI = bpR + 16 * S2_B_PITCH;
                uint32_t bi0 = *(const uint32_t*)(bpI);
                uint32_t bi1 = *(const uint32_t*)(bpI + 4 * S2_B_PITCH);
                mma_f16(accR[tn], ar[0], ar[1], ar[2], ar[3], br0, br1);
                mma_f16(accR[tn], ai[0], ai[1], ai[2], ai[3],
                        bi0 ^ 0x80008000u, bi1 ^ 0x80008000u);
                mma_f16(accI[tn], ar[0], ar[1], ar[2], ar[3], bi0, bi1);
                mma_f16(accI[tn], ai[0], ai[1], ai[2], ai[3], br0, br1);
            }
        }
        __syncthreads();
        buf ^= 1;
    }

    // epilogue: write fp16 spectra in stage3 layout.
    const float cfac = ((m == 0) ? 1.0f : 2.0f) * (AMSCALE / ((float)LL * WSCALE));
    const int mh  = m >> 1;
    const int pr  = (m & 1) ? (32 + mh) : mh;
    const int pi  = pr + 64;
    const int p2r = pr >> 1, slr = pr & 1;
    const int p2i = pi >> 1, sli = pi & 1;
#pragma unroll
    for (int tn = 0; tn < 4; tn++) {
        int c = e0 + wn * 32 + tn * 8 + tig * 2;
        int b0r = wm * 16 + gid;
#pragma unroll
        for (int h = 0; h < 2; h++) {
            int bb = b0r + h * 8;
            size_t baseR = (((size_t)bb * 64 + p2r) * DD) * 2 + slr;
            size_t baseI = (((size_t)bb * 64 + p2i) * DD) * 2 + sli;
            g_AmH[baseR + (size_t)(c)     * 2] = __float2half_rn(cfac * accR[tn][h * 2]);
            g_AmH[baseR + (size_t)(c + 1) * 2] = __float2half_rn(cfac * accR[tn][h * 2 + 1]);
            g_AmH[baseI + (size_t)(c)     * 2] = __float2half_rn(cfac * accI[tn][h * 2]);
            g_AmH[baseI + (size_t)(c + 1) * 2] = __float2half_rn(cfac * accI[tn][h * 2 + 1]);
        }
    }
}

// ===========================================================================
// Stage 3 (double-folded, fp16 MMA m16n8k16) — monolithic grid (8,16,32).
// ===========================================================================
#define T3H_A_BYTES (64 * 272)
#define T3H_B_BYTES (64 * 272)
#define T3H_SMEM (T3H_A_BYTES + T3H_B_BYTES)   // 34816

__global__ __launch_bounds__(256, 2) void fno_stage3_fold2(float* __restrict__ out) {
    extern __shared__ char smc[];
    const int b  = blockIdx.z;
    const int l0 = blockIdx.y * 64;
    const int n0 = blockIdx.x * 64;
    const int tid = threadIdx.x;
    const int warp = tid >> 5, lane = tid & 31;
    const int wm = warp >> 2, wn = warp & 3;
    const int gid = lane >> 2, tig = lane & 3;
    const uint32_t smem_u = (uint32_t)__cvta_generic_to_shared(smc);
    const char* As = smc;
    const char* Bs = smc + T3H_A_BYTES;
    const __half2* gah = (const __half2*)g_AmH;

    {
        uint32_t aB = smem_u;
        uint32_t bB = smem_u + T3H_A_BYTES;
#pragma unroll
        for (int i = 0; i < 4; i++) {
            int idx = tid + i * 256;
            int row = idx >> 4, c16 = idx & 15;
            cp16(aB + row * 272 + c16 * 16, &g_S3FH[(l0 + row) * 128 + c16 * 8]);
        }
#pragma unroll
        for (int i = 0; i < 4; i++) {
            int idx = tid + i * 256;
            int row = idx >> 4, c4 = idx & 15;
            cp16(bB + row * 272 + c4 * 16,
                 &gah[((size_t)(b * 64 + row)) * DD + n0 + c4 * 4]);
        }
        cp_commit();
        asm volatile("cp.async.wait_group 0;");
        __syncthreads();
    }

    float aCE[2][2][4], aCO[2][2][4], aSE[2][2][4], aSO[2][2][4];
#pragma unroll
    for (int i = 0; i < 2; i++)
#pragma unroll
        for (int j = 0; j < 2; j++)
#pragma unroll
            for (int k = 0; k < 4; k++) {
                aCE[i][j][k] = 0.0f; aCO[i][j][k] = 0.0f;
                aSE[i][j][k] = 0.0f; aSO[i][j][k] = 0.0f;
            }

#pragma unroll
    for (int ks = 0; ks < 8; ks++) {
        uint32_t a[2][4];
#pragma unroll
        for (int tm = 0; tm < 2; tm++) {
            const char* ap = As + (wm * 32 + tm * 16 + gid) * 272 + (ks * 16 + 2 * tig) * 2;
            a[tm][0] = *(const uint32_t*)(ap);
            a[tm][1] = *(const uint32_t*)(ap + 8 * 272);
            a[tm][2] = *(const uint32_t*)(ap + 16);
            a[tm][3] = *(const uint32_t*)(ap + 8 * 272 + 16);
        }
        uint32_t bf[2][2];
#pragma unroll
        for (int tn = 0; tn < 2; tn++) {
            const char* bp = Bs + (ks * 8 + tig) * 272 + (wn * 16 + tn * 8 + gid) * 4;
            bf[tn][0] = *(const uint32_t*)(bp);
            bf[tn][1] = *(const uint32_t*)(bp + 4 * 272);
        }
        if (ks < 2) {
#pragma unroll
            for (int tm = 0; tm < 2; tm++)
#pragma unroll
                for (int tn = 0; tn < 2; tn++)
                    mma_f16(aCE[tm][tn], a[tm][0], a[tm][1], a[tm][2], a[tm][3],
                            bf[tn][0], bf[tn][1]);
        } else if (ks < 4) {
#pragma unroll
            for (int tm = 0; tm < 2; tm++)
#pragma unroll
                for (int tn = 0; tn < 2; tn++)
                    mma_f16(aCO[tm][tn], a[tm][0], a[tm][1], a[tm][2], a[tm][3],
                            bf[tn][0], bf[tn][1]);
        } else if (ks < 6) {
#pragma unroll
            for (int tm = 0; tm < 2; tm++)
#pragma unroll
                for (int tn = 0; tn < 2; tn++)
                    mma_f16(aSE[tm][tn], a[tm][0], a[tm][1], a[tm][2], a[tm][3],
                            bf[tn][0], bf[tn][1]);
        } else {
#pragma unroll
            for (int tm = 0; tm < 2; tm++)
#pragma unroll
                for (int tn = 0; tn < 2; tn++)
                    mma_f16(aSO[tm][tn], a[tm][0], a[tm][1], a[tm][2], a[tm][3],
                            bf[tn][0], bf[tn][1]);
        }
    }

    float* ob = out + (size_t)b * LL * DD;
#pragma unroll
    for (int tm = 0; tm < 2; tm++) {
        int lA = l0 + wm * 32 + tm * 16 + gid;
#pragma unroll
        for (int tn = 0; tn < 2; tn++) {
            int c = n0 + wn * 16 + tn * 8 + tig * 2;
#pragma unroll
            for (int h = 0; h < 2; h++) {
                int l = lA + h * 8;
                float ce0 = aCE[tm][tn][h * 2],     ce1 = aCE[tm][tn][h * 2 + 1];
                float co0 = aCO[tm][tn][h * 2],     co1 = aCO[tm][tn][h * 2 + 1];
                float se0 = aSE[tm][tn][h * 2],     se1 = aSE[tm][tn][h * 2 + 1];
                float so0 = aSO[tm][tn][h * 2],     so1 = aSO[tm][tn][h * 2 + 1];
                *(float2*)&ob[(size_t)l * DD + c] =
                    make_float2((ce0 + co0 + se0 + so0) * INV_AMSCALE,
                                (ce1 + co1 + se1 + so1) * INV_AMSCALE);
                *(float2*)&ob[(size_t)(2048 - l) * DD + c] =
                    make_float2((ce0 - co0 - se0 + so0) * INV_AMSCALE,
                                (ce1 - co1 - se1 + so1) * INV_AMSCALE);
                *(float2*)&ob[(size_t)(2048 + l) * DD + c] =
                    make_float2((ce0 - co0 + se0 - so0) * INV_AMSCALE,
                                (ce1 - co1 + se1 - so1) * INV_AMSCALE);
                if (l > 0)
                    *(float2*)&ob[(size_t)(LL - l) * DD + c] =
                        make_float2((ce0 + co0 - se0 - so0) * INV_AMSCALE,
                                    (ce1 + co1 - se1 - so1) * INV_AMSCALE);
            }
        }
    }
}

// ---------------------------------------------------------------------------
// Rows l=1024 and l=3072
// ---------------------------------------------------------------------------
__global__ void fno_rows_special(float* __restrict__ out) {
    int b = blockIdx.y;
    int e = blockIdx.x * 128 + threadIdx.x;
    float C = 0.0f, S = 0.0f;
#pragma unroll
    for (int j = 0; j < 32; j++) {
        float sgn = (j & 1) ? -1.0f : 1.0f;
        float ar = __half2float(g_AmH[(((size_t)b * 64 + (j >> 1)) * DD + e) * 2 + (j & 1)]);
        float ai = __half2float(g_AmH[(((size_t)b * 64 + 48 + (j >> 1)) * DD + e) * 2 + (j & 1)]);
        C += sgn * ar;
        S -= sgn * ai;
    }
    out[((size_t)b * LL + 1024) * DD + e] = (C + S) * INV_AMSCALE;
    out[((size_t)b * LL + 3072) * DD + e] = (C - S) * INV_AMSCALE;
}

// ---------------------------------------------------------------------------
// Launch (R11 structure): transpose forked onto side stream overlapping
// stage1; rows_special forked onto side stream overlapping stage3.
// ---------------------------------------------------------------------------
extern "C" void kernel_launch(void* const* d_in, const int* in_sizes, int n_in,
                              void* d_out, int out_size) {
    (void)in_sizes; (void)n_in; (void)out_size;
    const float* q  = (const float*)d_in[0];
    const float* wr = (const float*)d_in[1];
    const float* wi = (const float*)d_in[2];
    float* out = (float*)d_out;

    static bool init_done = false;
    static cudaStream_t s_side;
    static cudaEvent_t ev_fork, ev_join, ev_fork2, ev_join2;
    if (!init_done) {
        cudaFuncSetAttribute(fno_stage1_fold,
                             cudaFuncAttributeMaxDynamicSharedMemorySize, S1F_SMEM);
        cudaFuncSetAttribute(fno_stage2_mma,
                             cudaFuncAttributeMaxDynamicSharedMemorySize, S2_SMEM);
        cudaFuncSetAttribute(fno_stage3_fold2,
                             cudaFuncAttributeMaxDynamicSharedMemorySize, T3H_SMEM);
        cudaStreamCreateWithFlags(&s_side, cudaStreamNonBlocking);
        cudaEventCreateWithFlags(&ev_fork, cudaEventDisableTiming);
        cudaEventCreateWithFlags(&ev_join, cudaEventDisableTiming);
        cudaEventCreateWithFlags(&ev_fork2, cudaEventDisableTiming);
        cudaEventCreateWithFlags(&ev_join2, cudaEventDisableTiming);
        init_done = true;
    }

    // main: tables
    fno_init<<<(F1_CNT + S3F_CNT + 255) / 256, 256>>>();

    // fork: transpose on side stream, concurrent with stage1
    cudaEventRecord(ev_fork, 0);
    cudaStreamWaitEvent(s_side, ev_fork, 0);
    fno_transpose_w<<<dim3(16, 2, 256), dim3(32, 8), 0, s_side>>>(wr, wi);

    fno_stage1_fold<<<dim3(8, 32), 256, S1F_SMEM>>>(q);

    // join: stage2 needs g_QH (main) and g_W2 (side)
    cudaEventRecord(ev_join, s_side);
    cudaStreamWaitEvent(0, ev_join, 0);

    fno_stage2_mma<<<dim3(4, 64), 256, S2_SMEM>>>();

    // fork: rows_special on side stream, concurrent with stage3
    cudaEventRecord(ev_fork2, 0);
    cudaStreamWaitEvent(s_side, ev_fork2, 0);
    fno_rows_special<<<dim3(4, 32), 128, 0, s_side>>>(out);

    fno_stage3_fold2<<<dim3(8, 16, 32), 256, T3H_SMEM>>>(out);

    // join: out complete on main stream
    cudaEventRecord(ev_join2, s_side);
    cudaStreamWaitEvent(0, ev_join2, 0);
}

// round 16
// speedup vs baseline: 1.5481x; 1.1291x over previous
#include <cuda_runtime.h>
#include <cuda_bf16.h>
#include <cuda_fp16.h>
#include <cstdint>

// Problem constants
#define BB 32
#define LL 4096
#define DD 512
#define MODES 64
#define NK 128          // 2*MODES (real rows + imag rows)
#define WSCALE 16384.0f // 2^14 fp16 range scaling for weights
#define AMSCALE 33554432.0f   // 2^25 fp16 range scaling for spectra
#define INV_AMSCALE (1.0f / 33554432.0f)

// ---------------------------------------------------------------------------
// Static device scratch
// ---------------------------------------------------------------------------
__device__ __half  g_F1H[NK * 2048];             // folded fwd tables fp16 [128][2048], l=j+1
__device__ __half  g_S3FH[1024 * 128];           // folded inv tables fp16
__device__ __half2 g_W2[2ull * MODES * 256 * DD];// [ri][m][d2][e] d-pair-interleaved, x2^14
__device__ __half  g_QH[BB * NK * DD];           // [b][row][d] fp16 spectra of q
__device__ __half  g_AmH[BB * 64 * DD * 2];      // [b][p2][e][slot] fp16, permuted+pair-interleaved, x2^25

// ---------------------------------------------------------------------------
// Helpers
// ---------------------------------------------------------------------------
__device__ __forceinline__ void mma_f16(float c[4],
                                        uint32_t a0, uint32_t a1, uint32_t a2, uint32_t a3,
                                        uint32_t b0, uint32_t b1) {
    asm volatile(
        "mma.sync.aligned.m16n8k16.row.col.f32.f16.f16.f32 "
        "{%0,%1,%2,%3}, {%4,%5,%6,%7}, {%8,%9}, {%0,%1,%2,%3};"
        : "+f"(c[0]), "+f"(c[1]), "+f"(c[2]), "+f"(c[3])
        : "r"(a0), "r"(a1), "r"(a2), "r"(a3), "r"(b0), "r"(b1));
}

__device__ __forceinline__ void cp16(uint32_t dst_smem, const void* src) {
    asm volatile("cp.async.cg.shared.global [%0], [%1], 16;" :: "r"(dst_smem), "l"(src));
}
__device__ __forceinline__ void cp_commit() { asm volatile("cp.async.commit_group;"); }

// ---------------------------------------------------------------------------
// Init: all twiddle tables in one launch.
// ---------------------------------------------------------------------------
#define F1_CNT (NK * 2048)
#define S3F_CNT (1024 * 128)

__global__ void fno_init() {
    int idx = blockIdx.x * blockDim.x + threadIdx.x;
    if (idx < F1_CNT) {
        int row = idx >> 11;
        int j   = idx & 2047;
        int l   = j + 1;
        int m   = row & (MODES - 1);
        int r   = (m * l) & (LL - 1);
        float s, c;
        sincospif((float)r * (1.0f / 2048.0f), &s, &c);
        g_F1H[row * 2048 + j] = __float2half_rn((row < MODES) ? c : -s);
    } else if (idx < F1_CNT + S3F_CNT) {
        int i2 = idx - F1_CNT;
        int l  = i2 >> 7;
        int cc = i2 & 127;
        int grp = cc >> 5;            // 0 cosE, 1 cosO, 2 -sinE, 3 -sinO
        int m  = ((cc & 31) << 1) + (grp & 1);
        int r  = (m * l) & (LL - 1);
        float s, c;
        sincospif((float)r * (1.0f / 2048.0f), &s, &c);
        g_S3FH[l * 128 + cc] = __float2half_rn((grp < 2) ? c : -s);
    }
}

// ---------------------------------------------------------------------------
// Weight transpose: g_W2[ri][m][d2][e] = half2(w_ri[2*d2][e][m], w_ri[2*d2+1][e][m]) * 2^14
// grid (16 e-tiles, 2 m-tiles, 256 d-pairs), block (32,8).
// ---------------------------------------------------------------------------
__global__ void fno_transpose_w(const float* __restrict__ wr,
                                const float* __restrict__ wi) {
    __shared__ float t[2][2][32][33];   // [ri][dd][e-idx][m-idx]
    int z  = blockIdx.z;                // d-pair index
    int e0 = blockIdx.x * 32;
    int m0 = blockIdx.y * 32;
    int tx = threadIdx.x, ty = threadIdx.y;
#pragma unroll
    for (int dd = 0; dd < 2; dd++) {
        int d = 2 * z + dd;
        size_t src = ((size_t)d * DD) * MODES + m0;
        for (int i = ty; i < 32; i += 8) {
            t[0][dd][i][tx] = wr[src + (size_t)(e0 + i) * MODES + tx];
            t[1][dd][i][tx] = wi[src + (size_t)(e0 + i) * MODES + tx];
        }
    }
    __syncthreads();
    for (int i = ty; i < 32; i += 8) {
        int m = m0 + i;
        size_t dstR = (((size_t)m) * 256 + z) * DD + e0 + tx;
        size_t dstI = dstR + (size_t)MODES * 256 * DD;
        g_W2[dstR] = __floats2half2_rn(t[0][0][tx][i] * WSCALE, t[0][1][tx][i] * WSCALE);
        g_W2[dstI] = __floats2half2_rn(t[1][0][tx][i] * WSCALE, t[1][1][tx][i] * WSCALE);
    }
}

// ===========================================================================
// Stage 1 (folded, fp16 MMA m16n8k16, BN=64): per-batch
//   Qr[64,512] = cosF[64,2048] x P[2048,512]   (+ q[0,:] correction)
//   Qi[64,512] = (-sinF)[64,2048] x D[2048,512]
// P[j] = q[j+1] + q[4096-(j+1)], D[j] = q[j+1] - q[...]; j=2047 (l=2048) is
// self-paired: partner term is zero (P = q[2048], D = q[2048]).
// grid (8 n-tiles, 32 b), block 256. Warp tile 64x16.
// ===========================================================================
#define S1H_A_PITCH 80
#define S1H_A_BYTES (128 * S1H_A_PITCH)    // 10240
#define S1H_B_PITCH 272
#define S1H_B_BYTES (16 * S1H_B_PITCH)     // 4352 (per P or D)
#define S1H_BUF (S1H_A_BYTES + 2 * S1H_B_BYTES)  // 18944
#define S1H_SMEM (2 * S1H_BUF)             // 37888

__global__ __launch_bounds__(256, 2) void fno_stage1_fold(const float* __restrict__ q) {
    extern __shared__ char smc[];
    const int b  = blockIdx.y;
    const int n0 = blockIdx.x * 64;
    const float* qb = q + (size_t)b * LL * DD;
    const int tid = threadIdx.x;
    const int warp = tid >> 5, lane = tid & 31;
    const int wm = warp >> 2, wn = warp & 3;
    const int gid = lane >> 2, tig = lane & 3;
    const uint32_t smu = (uint32_t)__cvta_generic_to_shared(smc);

    float acc[4][2][4];
#pragma unroll
    for (int i = 0; i < 4; i++)
#pragma unroll
        for (int j = 0; j < 2; j++)
#pragma unroll
            for (int k = 0; k < 4; k++) acc[i][j][k] = 0.0f;

    // B loader: thread -> k-pair j2 = tid>>4 (16), n-group nc = tid&15 (4 n each)
    const int j2 = tid >> 4, nc = tid & 15;
    float4 va1, vb1, va2, vb2;
    auto ldB = [&](int k0) {
        int l1 = k0 + 2 * j2 + 1;
        int l2 = l1 + 1;
        va1 = *(const float4*)&qb[(size_t)l1 * DD + n0 + nc * 4];
        vb1 = *(const float4*)&qb[(size_t)(LL - l1) * DD + n0 + nc * 4];
        // l=2048 is self-paired: keep q[2048], zero only the partner term.
        va2 = *(const float4*)&qb[(size_t)l2 * DD + n0 + nc * 4];
        vb2 = (l2 == 2048) ? make_float4(0.f, 0.f, 0.f, 0.f)
                           : *(const float4*)&qb[(size_t)(LL - l2) * DD + n0 + nc * 4];
    };
    auto stB = [&](int buf) {
        char* P  = smc + buf * S1H_BUF + S1H_A_BYTES;
        char* Dn = P + S1H_B_BYTES;
        __half2 ph[4], dh[4];
        const float* a1 = &va1.x; const float* b1 = &vb1.x;
        const float* a2 = &va2.x; const float* b2 = &vb2.x;
#pragma unroll
        for (int n = 0; n < 4; n++) {
            ph[n] = __floats2half2_rn(a1[n] + b1[n], a2[n] + b2[n]);
            dh[n] = __floats2half2_rn(a1[n] - b1[n], a2[n] - b2[n]);
        }
        *(uint4*)(P  + j2 * S1H_B_PITCH + nc * 16) = *(uint4*)ph;
        *(uint4*)(Dn + j2 * S1H_B_PITCH + nc * 16) = *(uint4*)dh;
    };
    auto cpA = [&](int buf, int k0) {
        uint32_t aB = smu + buf * S1H_BUF;
#pragma unroll
        for (int i = 0; i < 2; i++) {
            int idx = tid + i * 256;
            int row = idx >> 2, c16 = idx & 3;
            cp16(aB + row * S1H_A_PITCH + c16 * 16,
                 &g_F1H[row * 2048 + k0 + c16 * 8]);
        }
        cp_commit();
    };

    cpA(0, 0);
    ldB(0);
    const int NT = 64;          // 2048 / 32
    for (int kt = 0; kt < NT; kt++) {
        int buf = kt & 1;
        stB(buf);
        if (kt + 1 < NT) {
            cpA(buf ^ 1, (kt + 1) * 32);
            asm volatile("cp.async.wait_group 1;");
        } else {
            asm volatile("cp.async.wait_group 0;");
        }
        __syncthreads();
        if (kt + 1 < NT) ldB((kt + 1) * 32);

        const char* As = smc + buf * S1H_BUF;
        const char* Bs = As + S1H_A_BYTES + wm * S1H_B_BYTES;  // P or D
#pragma unroll
        for (int ks = 0; ks < 2; ks++) {       // two K=16 steps per 32-k chunk
            uint32_t a[4][4];
#pragma unroll
            for (int tm = 0; tm < 4; tm++) {
                const char* ap = As + (wm * 64 + tm * 16 + gid) * S1H_A_PITCH
                               + ks * 32 + tig * 4;
                a[tm][0] = *(const uint32_t*)(ap);
                a[tm][1] = *(const uint32_t*)(ap + 8 * S1H_A_PITCH);
                a[tm][2] = *(const uint32_t*)(ap + 16);
                a[tm][3] = *(const uint32_t*)(ap + 8 * S1H_A_PITCH + 16);
            }
            uint32_t bf[2][2];
#pragma unroll
            for (int tn = 0; tn < 2; tn++) {
                const char* bp = Bs + (ks * 8 + tig) * S1H_B_PITCH
                               + (wn * 16 + tn * 8 + gid) * 4;
                bf[tn][0] = *(const uint32_t*)(bp);
                bf[tn][1] = *(const uint32_t*)(bp + 4 * S1H_B_PITCH);
            }
#pragma unroll
            for (int tm = 0; tm < 4; tm++)
#pragma unroll
                for (int tn = 0; tn < 2; tn++)
                    mma_f16(acc[tm][tn], a[tm][0], a[tm][1], a[tm][2], a[tm][3],
                            bf[tn][0], bf[tn][1]);
        }
        __syncthreads();
    }

#pragma unroll
    for (int tm = 0; tm < 4; tm++) {
        int r = wm * 64 + tm * 16 + gid;
#pragma unroll
        for (int tn = 0; tn < 2; tn++) {
            int c = n0 + wn * 16 + tn * 8 + tig * 2;
            float c0 = 0.f, c1 = 0.f;
            if (wm == 0) { c0 = qb[c]; c1 = qb[c + 1]; }
            *(__half2*)&g_QH[((size_t)b * NK + r) * DD + c] =
                __floats2half2_rn(acc[tm][tn][0] + c0, acc[tm][tn][1] + c1);
            *(__half2*)&g_QH[((size_t)b * NK + r + 8) * DD + c] =
                __floats2half2_rn(acc[tm][tn][2] + c0, acc[tm][tn][3] + c1);
        }
    }
}

// ---------------------------------------------------------------------------
// Stage 2 (fp16 MMA m16n8k16): per-mode complex GEMM, monolithic grid (4,64).
// ---------------------------------------------------------------------------
#define S2_A_PITCH 80                      // bytes/row
#define S2_B_PITCH 560                     // bytes/row
#define S2_A_BYTES (64 * S2_A_PITCH)       // 5120
#define S2_B_BYTES (32 * S2_B_PITCH)       // 17920
#define S2_BUF_BYTES (S2_A_BYTES + S2_B_BYTES)
#define S2_SMEM (2 * S2_BUF_BYTES)         // 46080

__global__ __launch_bounds__(256) void fno_stage2_mma() {
    extern __shared__ char smc[];
    const int m  = blockIdx.y;
    const int e0 = blockIdx.x * 128;
    const int tid = threadIdx.x;
    const int warp = tid >> 5, lane = tid & 31;
    const int wm = warp >> 2;
    const int wn = warp & 3;
    const int gid = lane >> 2, tig = lane & 3;
    const uint32_t smem_u = (uint32_t)__cvta_generic_to_shared(smc);

    float accR[4][4], accI[4][4];
#pragma unroll
    for (int i = 0; i < 4; i++)
#pragma unroll
        for (int j = 0; j < 4; j++) { accR[i][j] = 0.0f; accI[i][j] = 0.0f; }

    auto load_tiles = [&](int buf, int kt) {
        uint32_t aB = smem_u + buf * S2_BUF_BYTES;
        uint32_t bB = aB + S2_A_BYTES;
        int d0 = kt * 32;
        {
            int row = tid >> 2, c16 = tid & 3;
            int ri = row >> 5, bb = row & 31;
            cp16(aB + row * S2_A_PITCH + c16 * 16,
                 &g_QH[((size_t)bb * NK + ri * MODES + m) * DD + d0 + c16 * 8]);
        }
#pragma unroll
        for (int i = 0; i < 4; i++) {
            int idx = tid + i * 256;
            int row = idx >> 5, c = idx & 31;
            int ri = row >> 4, dr = row & 15;
            int d2 = kt * 16 + dr;
            cp16(bB + row * S2_B_PITCH + c * 16,
                 &g_W2[(((size_t)ri * MODES + m) * 256 + d2) * DD + e0 + c * 4]);
        }
        cp_commit();
    };

    load_tiles(0, 0);
    int buf = 0;
    const int NT = 16;
    for (int kt = 0; kt < NT; kt++) {
        if (kt + 1 < NT) {
            load_tiles(buf ^ 1, kt + 1);
            asm volatile("cp.async.wait_group 1;");
        } else {
            asm volatile("cp.async.wait_group 0;");
        }
        __syncthreads();
        const char* As = smc + buf * S2_BUF_BYTES;
        const char* Bs = As + S2_A_BYTES;
#pragma unroll
        for (int ks = 0; ks < 2; ks++) {
            uint32_t ar[4], ai[4];
            {
                const char* ap = As + (wm * 16 + gid) * S2_A_PITCH + ks * 32 + tig * 4;
                ar[0] = *(const uint32_t*)(ap);
                ar[1] = *(const uint32_t*)(ap + 8 * S2_A_PITCH);
                ar[2] = *(const uint32_t*)(ap + 16);
                ar[3] = *(const uint32_t*)(ap + 8 * S2_A_PITCH + 16);
                const char* aq = ap + 32 * S2_A_PITCH;
                ai[0] = *(const uint32_t*)(aq);
                ai[1] = *(const uint32_t*)(aq + 8 * S2_A_PITCH);
                ai[2] = *(const uint32_t*)(aq + 16);
                ai[3] = *(const uint32_t*)(aq + 8 * S2_A_PITCH + 16);
            }
#pragma unroll
            for (int tn = 0; tn < 4; tn++) {
                const char* bpR = Bs + (ks * 8 + tig) * S2_B_PITCH + (wn * 32 + tn * 8 + gid) * 4;
                uint32_t br0 = *(const uint32_t*)(bpR);
                uint32_t br1 = *(const uint32_t*)(bpR + 4 * S2_B_PITCH);
                const char* bpI = bpR + 16 * S2_B_PITCH;
                uint32_t bi0 = *(const uint32_t*)(bpI);
                uint32_t bi1 = *(const uint32_t*)(bpI + 4 * S2_B_PITCH);
                mma_f16(accR[tn], ar[0], ar[1], ar[2], ar[3], br0, br1);
                mma_f16(accR[tn], ai[0], ai[1], ai[2], ai[3],
                        bi0 ^ 0x80008000u, bi1 ^ 0x80008000u);
                mma_f16(accI[tn], ar[0], ar[1], ar[2], ar[3], bi0, bi1);
                mma_f16(accI[tn], ai[0], ai[1], ai[2], ai[3], br0, br1);
            }
        }
        __syncthreads();
        buf ^= 1;
    }

    // epilogue: write fp16 spectra in stage3 layout.
    const float cfac = ((m == 0) ? 1.0f : 2.0f) * (AMSCALE / ((float)LL * WSCALE));
    const int mh  = m >> 1;
    const int pr  = (m & 1) ? (32 + mh) : mh;
    const int pi  = pr + 64;
    const int p2r = pr >> 1, slr = pr & 1;
    const int p2i = pi >> 1, sli = pi & 1;
#pragma unroll
    for (int tn = 0; tn < 4; tn++) {
        int c = e0 + wn * 32 + tn * 8 + tig * 2;
        int b0r = wm * 16 + gid;
#pragma unroll
        for (int h = 0; h < 2; h++) {
            int bb = b0r + h * 8;
            size_t baseR = (((size_t)bb * 64 + p2r) * DD) * 2 + slr;
            size_t baseI = (((size_t)bb * 64 + p2i) * DD) * 2 + sli;
            g_AmH[baseR + (size_t)(c)     * 2] = __float2half_rn(cfac * accR[tn][h * 2]);
            g_AmH[baseR + (size_t)(c + 1) * 2] = __float2half_rn(cfac * accR[tn][h * 2 + 1]);
            g_AmH[baseI + (size_t)(c)     * 2] = __float2half_rn(cfac * accI[tn][h * 2]);
            g_AmH[baseI + (size_t)(c + 1) * 2] = __float2half_rn(cfac * accI[tn][h * 2 + 1]);
        }
    }
}

// ===========================================================================
// Stage 3 (double-folded, fp16 MMA m16n8k16) — monolithic grid (8,16,32).
// ===========================================================================
#define T3H_A_BYTES (64 * 272)
#define T3H_B_BYTES (64 * 272)
#define T3H_SMEM (T3H_A_BYTES + T3H_B_BYTES)   // 34816

__global__ __launch_bounds__(256, 2) void fno_stage3_fold2(float* __restrict__ out) {
    extern __shared__ char smc[];
    const int b  = blockIdx.z;
    const int l0 = blockIdx.y * 64;
    const int n0 = blockIdx.x * 64;
    const int tid = threadIdx.x;
    const int warp = tid >> 5, lane = tid & 31;
    const int wm = warp >> 2, wn = warp & 3;
    const int gid = lane >> 2, tig = lane & 3;
    const uint32_t smem_u = (uint32_t)__cvta_generic_to_shared(smc);
    const char* As = smc;
    const char* Bs = smc + T3H_A_BYTES;
    const __half2* gah = (const __half2*)g_AmH;

    {
        uint32_t aB = smem_u;
        uint32_t bB = smem_u + T3H_A_BYTES;
#pragma unroll
        for (int i = 0; i < 4; i++) {
            int idx = tid + i * 256;
            int row = idx >> 4, c16 = idx & 15;
            cp16(aB + row * 272 + c16 * 16, &g_S3FH[(l0 + row) * 128 + c16 * 8]);
        }
#pragma unroll
        for (int i = 0; i < 4; i++) {
            int idx = tid + i * 256;
            int row = idx >> 4, c4 = idx & 15;
            cp16(bB + row * 272 + c4 * 16,
                 &gah[((size_t)(b * 64 + row)) * DD + n0 + c4 * 4]);
        }
        cp_commit();
        asm volatile("cp.async.wait_group 0;");
        __syncthreads();
    }

    float aCE[2][2][4], aCO[2][2][4], aSE[2][2][4], aSO[2][2][4];
#pragma unroll
    for (int i = 0; i < 2; i++)
#pragma unroll
        for (int j = 0; j < 2; j++)
#pragma unroll
            for (int k = 0; k < 4; k++) {
                aCE[i][j][k] = 0.0f; aCO[i][j][k] = 0.0f;
                aSE[i][j][k] = 0.0f; aSO[i][j][k] = 0.0f;
            }

#pragma unroll
    for (int ks = 0; ks < 8; ks++) {
        uint32_t a[2][4];
#pragma unroll
        for (int tm = 0; tm < 2; tm++) {
            const char* ap = As + (wm * 32 + tm * 16 + gid) * 272 + (ks * 16 + 2 * tig) * 2;
            a[tm][0] = *(const uint32_t*)(ap);
            a[tm][1] = *(const uint32_t*)(ap + 8 * 272);
            a[tm][2] = *(const uint32_t*)(ap + 16);
            a[tm][3] = *(const uint32_t*)(ap + 8 * 272 + 16);
        }
        uint32_t bf[2][2];
#pragma unroll
        for (int tn = 0; tn < 2; tn++) {
            const char* bp = Bs + (ks * 8 + tig) * 272 + (wn * 16 + tn * 8 + gid) * 4;
            bf[tn][0] = *(const uint32_t*)(bp);
            bf[tn][1] = *(const uint32_t*)(bp + 4 * 272);
        }
        if (ks < 2) {
#pragma unroll
            for (int tm = 0; tm < 2; tm++)
#pragma unroll
                for (int tn = 0; tn < 2; tn++)
                    mma_f16(aCE[tm][tn], a[tm][0], a[tm][1], a[tm][2], a[tm][3],
                            bf[tn][0], bf[tn][1]);
        } else if (ks < 4) {
#pragma unroll
            for (int tm = 0; tm < 2; tm++)
#pragma unroll
                for (int tn = 0; tn < 2; tn++)
                    mma_f16(aCO[tm][tn], a[tm][0], a[tm][1], a[tm][2], a[tm][3],
                            bf[tn][0], bf[tn][1]);
        } else if (ks < 6) {
#pragma unroll
            for (int tm = 0; tm < 2; tm++)
#pragma unroll
                for (int tn = 0; tn < 2; tn++)
                    mma_f16(aSE[tm][tn], a[tm][0], a[tm][1], a[tm][2], a[tm][3],
                            bf[tn][0], bf[tn][1]);
        } else {
#pragma unroll
            for (int tm = 0; tm < 2; tm++)
#pragma unroll
                for (int tn = 0; tn < 2; tn++)
                    mma_f16(aSO[tm][tn], a[tm][0], a[tm][1], a[tm][2], a[tm][3],
                            bf[tn][0], bf[tn][1]);
        }
    }

    float* ob = out + (size_t)b * LL * DD;
#pragma unroll
    for (int tm = 0; tm < 2; tm++) {
        int lA = l0 + wm * 32 + tm * 16 + gid;
#pragma unroll
        for (int tn = 0; tn < 2; tn++) {
            int c = n0 + wn * 16 + tn * 8 + tig * 2;
#pragma unroll
            for (int h = 0; h < 2; h++) {
                int l = lA + h * 8;
                float ce0 = aCE[tm][tn][h * 2],     ce1 = aCE[tm][tn][h * 2 + 1];
                float co0 = aCO[tm][tn][h * 2],     co1 = aCO[tm][tn][h * 2 + 1];
                float se0 = aSE[tm][tn][h * 2],     se1 = aSE[tm][tn][h * 2 + 1];
                float so0 = aSO[tm][tn][h * 2],     so1 = aSO[tm][tn][h * 2 + 1];
                *(float2*)&ob[(size_t)l * DD + c] =
                    make_float2((ce0 + co0 + se0 + so0) * INV_AMSCALE,
                                (ce1 + co1 + se1 + so1) * INV_AMSCALE);
                *(float2*)&ob[(size_t)(2048 - l) * DD + c] =
                    make_float2((ce0 - co0 - se0 + so0) * INV_AMSCALE,
                                (ce1 - co1 - se1 + so1) * INV_AMSCALE);
                *(float2*)&ob[(size_t)(2048 + l) * DD + c] =
                    make_float2((ce0 - co0 + se0 - so0) * INV_AMSCALE,
                                (ce1 - co1 + se1 - so1) * INV_AMSCALE);
                if (l > 0)
                    *(float2*)&ob[(size_t)(LL - l) * DD + c] =
                        make_float2((ce0 + co0 - se0 - so0) * INV_AMSCALE,
                                    (ce1 + co1 - se1 - so1) * INV_AMSCALE);
            }
        }
    }
}

// ---------------------------------------------------------------------------
// Rows l=1024 and l=3072
// ---------------------------------------------------------------------------
__global__ void fno_rows_special(float* __restrict__ out) {
    int b = blockIdx.y;
    int e = blockIdx.x * 128 + threadIdx.x;
    float C = 0.0f, S = 0.0f;
#pragma unroll
    for (int j = 0; j < 32; j++) {
        float sgn = (j & 1) ? -1.0f : 1.0f;
        float ar = __half2float(g_AmH[(((size_t)b * 64 + (j >> 1)) * DD + e) * 2 + (j & 1)]);
        float ai = __half2float(g_AmH[(((size_t)b * 64 + 48 + (j >> 1)) * DD + e) * 2 + (j & 1)]);
        C += sgn * ar;
        S -= sgn * ai;
    }
    out[((size_t)b * LL + 1024) * DD + e] = (C + S) * INV_AMSCALE;
    out[((size_t)b * LL + 3072) * DD + e] = (C - S) * INV_AMSCALE;
}

// ---------------------------------------------------------------------------
// Launch (R14 structure): transpose forked onto side stream overlapping
// stage1; rows_special forked onto side stream overlapping stage3.
// ---------------------------------------------------------------------------
extern "C" void kernel_launch(void* const* d_in, const int* in_sizes, int n_in,
                              void* d_out, int out_size) {
    (void)in_sizes; (void)n_in; (void)out_size;
    const float* q  = (const float*)d_in[0];
    const float* wr = (const float*)d_in[1];
    const float* wi = (const float*)d_in[2];
    float* out = (float*)d_out;

    static bool init_done = false;
    static cudaStream_t s_side;
    static cudaEvent_t ev_fork, ev_join, ev_fork2, ev_join2;
    if (!init_done) {
        cudaFuncSetAttribute(fno_stage1_fold,
                             cudaFuncAttributeMaxDynamicSharedMemorySize, S1H_SMEM);
        cudaFuncSetAttribute(fno_stage2_mma,
                             cudaFuncAttributeMaxDynamicSharedMemorySize, S2_SMEM);
        cudaFuncSetAttribute(fno_stage3_fold2,
                             cudaFuncAttributeMaxDynamicSharedMemorySize, T3H_SMEM);
        cudaStreamCreateWithFlags(&s_side, cudaStreamNonBlocking);
        cudaEventCreateWithFlags(&ev_fork, cudaEventDisableTiming);
        cudaEventCreateWithFlags(&ev_join, cudaEventDisableTiming);
        cudaEventCreateWithFlags(&ev_fork2, cudaEventDisableTiming);
        cudaEventCreateWithFlags(&ev_join2, cudaEventDisableTiming);
        init_done = true;
    }

    // main: tables
    fno_init<<<(F1_CNT + S3F_CNT + 255) / 256, 256>>>();

    // fork: transpose on side stream, concurrent with stage1
    cudaEventRecord(ev_fork, 0);
    cudaStreamWaitEvent(s_side, ev_fork, 0);
    fno_transpose_w<<<dim3(16, 2, 256), dim3(32, 8), 0, s_side>>>(wr, wi);

    fno_stage1_fold<<<dim3(8, 32), 256, S1H_SMEM>>>(q);

    // join: stage2 needs g_QH (main) and g_W2 (side)
    cudaEventRecord(ev_join, s_side);
    cudaStreamWaitEvent(0, ev_join, 0);

    fno_stage2_mma<<<dim3(4, 64), 256, S2_SMEM>>>();

    // fork: rows_special on side stream, concurrent with stage3
    cudaEventRecord(ev_fork2, 0);
    cudaStreamWaitEvent(s_side, ev_fork2, 0);
    fno_rows_special<<<dim3(4, 32), 128, 0, s_side>>>(out);

    fno_stage3_fold2<<<dim3(8, 16, 32), 256, T3H_SMEM>>>(out);

    // join: out complete on main stream
    cudaEventRecord(ev_join2, s_side);
    cudaStreamWaitEvent(0, ev_join2, 0);
}